// round 4
// baseline (speedup 1.0000x reference)
#include <cuda_runtime.h>
#include <math.h>

#define N_NODES   200000
#define NODE_DIM  256
#define OUT_DIM   512
#define NUM_HEADS 8
#define HEAD_DIM  32
#define HID       256
#define N_GRAPHS  2000

// ---------------- scratch (static device globals; no runtime allocation) ----
__device__ float g_H   [(size_t)N_NODES * HID];       // hidden scratch (reused)
__device__ float g_Vwm [(size_t)N_NODES * HID];       // wm values
__device__ float g_Vws [(size_t)N_NODES * HID];       // ws values
__device__ float g_Swm [(size_t)N_NODES * NUM_HEADS]; // wm scores
__device__ float g_Sws [(size_t)N_NODES * NUM_HEADS]; // ws scores
__device__ int   g_gstart[N_GRAPHS + 1];
__device__ int   g_seg64;
__device__ float g_Awm [(size_t)N_GRAPHS * HID];
__device__ float g_Aws [(size_t)N_GRAPHS * HID];
__device__ float g_Amax[(size_t)N_GRAPHS * HID];
__device__ float g_R   [(size_t)N_GRAPHS * 3 * OUT_DIM];

// ---------------- generic tiled GEMM: C[M,N] = op(A[M,K]) @ W[K,N] (+bias) ---
// BM=128, BN=64, BK=16, 256 threads, 8x4 per-thread microtile.
template<bool RELU_OUT, bool RELU_IN, bool HAS_BIAS>
__global__ __launch_bounds__(256)
void gemm128x64(const float* __restrict__ A, int lda,
                const float* __restrict__ W, int ldw,
                const float* __restrict__ bias,
                float* __restrict__ C, int ldc,
                int M, int K)
{
    __shared__ __align__(16) float As[16][128];
    __shared__ __align__(16) float Bs[16][64];

    const int tid = threadIdx.x;
    const int tx  = tid & 15;    // 0..15 -> 4 cols each
    const int ty  = tid >> 4;    // 0..15 -> 8 rows each
    const int bm  = blockIdx.x * 128;
    const int bn  = blockIdx.y * 64;

    float acc[8][4];
    #pragma unroll
    for (int i = 0; i < 8; i++)
        #pragma unroll
        for (int j = 0; j < 4; j++) acc[i][j] = 0.0f;

    for (int k0 = 0; k0 < K; k0 += 16) {
        // load A tile (128 rows x 16 cols) as float4, store transposed As[k][m]
        #pragma unroll
        for (int it = 0; it < 2; it++) {
            int s   = tid + it * 256;       // 0..511 float4 slots
            int r   = s >> 2;               // row within tile 0..127
            int c4  = s & 3;                // which float4 of the 16-col stripe
            int row = bm + r;
            if (row >= M) row = M - 1;      // clamp (stores are guarded)
            float4 v = reinterpret_cast<const float4*>(A + (size_t)row * lda + k0)[c4];
            if (RELU_IN) {
                v.x = fmaxf(v.x, 0.f); v.y = fmaxf(v.y, 0.f);
                v.z = fmaxf(v.z, 0.f); v.w = fmaxf(v.w, 0.f);
            }
            As[c4 * 4 + 0][r] = v.x;
            As[c4 * 4 + 1][r] = v.y;
            As[c4 * 4 + 2][r] = v.z;
            As[c4 * 4 + 3][r] = v.w;
        }
        // load W tile (16 rows x 64 cols)
        {
            int r  = tid >> 4;   // 0..15
            int c4 = tid & 15;   // 0..15
            float4 v = *reinterpret_cast<const float4*>(W + (size_t)(k0 + r) * ldw + bn + c4 * 4);
            *reinterpret_cast<float4*>(&Bs[r][c4 * 4]) = v;
        }
        __syncthreads();

        #pragma unroll
        for (int kk = 0; kk < 16; kk++) {
            float4 a0 = *reinterpret_cast<const float4*>(&As[kk][ty * 8]);
            float4 a1 = *reinterpret_cast<const float4*>(&As[kk][ty * 8 + 4]);
            float4 b  = *reinterpret_cast<const float4*>(&Bs[kk][tx * 4]);
            float av[8] = {a0.x, a0.y, a0.z, a0.w, a1.x, a1.y, a1.z, a1.w};
            float bv[4] = {b.x, b.y, b.z, b.w};
            #pragma unroll
            for (int i = 0; i < 8; i++)
                #pragma unroll
                for (int j = 0; j < 4; j++)
                    acc[i][j] = fmaf(av[i], bv[j], acc[i][j]);
        }
        __syncthreads();
    }

    float bj[4];
    #pragma unroll
    for (int j = 0; j < 4; j++) bj[j] = HAS_BIAS ? bias[bn + tx * 4 + j] : 0.0f;

    #pragma unroll
    for (int i = 0; i < 8; i++) {
        int row = bm + ty * 8 + i;
        if (row < M) {
            #pragma unroll
            for (int j = 0; j < 4; j++) {
                float v = acc[i][j] + bj[j];
                if (RELU_OUT) v = fmaxf(v, 0.f);
                C[(size_t)row * ldc + bn + tx * 4 + j] = v;
            }
        }
    }
}

// ---------------- score layer: S[N,8] = H[N,256] @ w2[256,8] + b2 ------------
__global__ __launch_bounds__(256)
void score_kernel(const float* __restrict__ H, const float* __restrict__ w2,
                  const float* __restrict__ b2, float* __restrict__ S)
{
    __shared__ float w2s[HID * NUM_HEADS];
    __shared__ float b2s[NUM_HEADS];
    int tid = threadIdx.x;
    for (int i = tid; i < HID * NUM_HEADS; i += 256) w2s[i] = w2[i];
    if (tid < NUM_HEADS) b2s[tid] = b2[tid];
    __syncthreads();

    int warp = tid >> 5, lane = tid & 31;
    int node = blockIdx.x * 8 + warp;
    if (node >= N_NODES) return;

    float acc[NUM_HEADS];
    #pragma unroll
    for (int j = 0; j < NUM_HEADS; j++) acc[j] = 0.f;

    const float* h = H + (size_t)node * HID;
    #pragma unroll
    for (int r = 0; r < 8; r++) {
        int k = r * 32 + lane;
        float hv = h[k];
        #pragma unroll
        for (int j = 0; j < NUM_HEADS; j++) acc[j] = fmaf(hv, w2s[k * NUM_HEADS + j], acc[j]);
    }
    #pragma unroll
    for (int j = 0; j < NUM_HEADS; j++) {
        float v = acc[j];
        #pragma unroll
        for (int off = 16; off; off >>= 1) v += __shfl_xor_sync(0xFFFFFFFFu, v, off);
        if (lane == j) S[(size_t)node * NUM_HEADS + j] = v + b2s[j];
    }
}

// ---------------- seg dtype detection (int64 vs int32) -----------------------
// Values are graph ids < 2000. Under an int64 layout, every high word is 0.
// Under int32, entries 8000..9999 are ~80..99 (sorted uniform), i.e. nonzero.
__global__ void detect_seg(const int* __restrict__ p32)
{
    if (blockIdx.x == 0 && threadIdx.x == 0) {
        int nz = 0;
        for (int i = 4000; i < 5000; i++) nz |= p32[2 * i + 1];
        g_seg64 = (nz == 0) ? 1 : 0;
    }
}

// ---------------- graph ranges (seg is sorted) -------------------------------
__global__ void graph_bounds(const void* __restrict__ segv)
{
    int g = blockIdx.x * blockDim.x + threadIdx.x;
    if (g > N_GRAPHS) return;
    if (g == N_GRAPHS) { g_gstart[g] = N_NODES; return; }
    const int is64 = g_seg64;
    const long long* p64 = (const long long*)segv;
    const int*       p32 = (const int*)segv;
    int lo = 0, hi = N_NODES;
    while (lo < hi) {
        int mid = (lo + hi) >> 1;
        long long v = is64 ? p64[mid] : (long long)p32[mid];
        if (v < (long long)g) lo = mid + 1; else hi = mid;
    }
    g_gstart[g] = lo;
}

// ---------------- per-graph accumulation (block per graph, 256 threads) ------
__global__ __launch_bounds__(256)
void accumulate_kernel(const float* __restrict__ X)
{
    int g   = blockIdx.x;
    int s0  = g_gstart[g], s1 = g_gstart[g + 1];
    int tid = threadIdx.x;
    int n   = s1 - s0;

    __shared__ float red[32][NUM_HEADS];
    __shared__ float mh[NUM_HEADS], inv[NUM_HEADS];

    if (n == 0) {
        g_Awm [(size_t)g * HID + tid] = 0.f;
        g_Aws [(size_t)g * HID + tid] = 0.f;
        g_Amax[(size_t)g * HID + tid] = 0.f;
        return;
    }

    int h0 = tid & 7, grp = tid >> 3;  // 32 groups x 8 heads
    // pass 1: per-head max of wm scores
    float m = -INFINITY;
    for (int i = grp; i < n; i += 32)
        m = fmaxf(m, g_Swm[(size_t)(s0 + i) * NUM_HEADS + h0]);
    red[grp][h0] = m;
    __syncthreads();
    if (tid < NUM_HEADS) {
        float mm = -INFINITY;
        #pragma unroll
        for (int r = 0; r < 32; r++) mm = fmaxf(mm, red[r][tid]);
        mh[tid] = mm;
    }
    __syncthreads();
    // pass 2: per-head sum of exp
    float mloc = mh[h0];
    float se = 0.f;
    for (int i = grp; i < n; i += 32)
        se += __expf(g_Swm[(size_t)(s0 + i) * NUM_HEADS + h0] - mloc);
    red[grp][h0] = se;
    __syncthreads();
    if (tid < NUM_HEADS) {
        float s = 0.f;
        #pragma unroll
        for (int r = 0; r < 32; r++) s += red[r][tid];
        inv[tid] = 1.0f / s;
    }
    __syncthreads();

    // pass 3: channel-per-thread streaming accumulation
    int c = tid;
    int h = c >> 5;
    float mH = mh[h], invH = inv[h];
    float aw = 0.f, asum = 0.f, mx = -INFINITY;
    for (int i = s0; i < s1; i++) {
        float sw = g_Swm[(size_t)i * NUM_HEADS + h];
        float ww = __expf(sw - mH) * invH;
        float ss = g_Sws[(size_t)i * NUM_HEADS + h];
        float ws = 1.0f / (1.0f + __expf(-ss));
        aw   = fmaf(ww, g_Vwm[(size_t)i * HID + c], aw);
        asum = fmaf(ws, g_Vws[(size_t)i * HID + c], asum);
        mx   = fmaxf(mx, X[(size_t)i * HID + c]);
    }
    g_Awm [(size_t)g * HID + c] = aw;
    g_Aws [(size_t)g * HID + c] = asum;
    g_Amax[(size_t)g * HID + c] = mx;
}

// ---------------- launch -----------------------------------------------------
extern "C" void kernel_launch(void* const* d_in, const int* in_sizes, int n_in,
                              void* d_out, int out_size)
{
    const float* x   = (const float*)d_in[0];
    const void*  seg = d_in[1];

    // Weight base index: if num_graphs is passed as a (scalar) device input it
    // sits at index 2 and weights start at 3; otherwise weights start at 2.
    int base = 2;
    if (n_in >= 23 || (n_in > 2 && in_sizes[2] == 1)) base = 3;

    const float* wm_sw1 = (const float*)d_in[base + 0];
    const float* wm_sb1 = (const float*)d_in[base + 1];
    const float* wm_sw2 = (const float*)d_in[base + 2];
    const float* wm_sb2 = (const float*)d_in[base + 3];
    const float* wm_vw1 = (const float*)d_in[base + 4];
    const float* wm_vb1 = (const float*)d_in[base + 5];
    const float* wm_vw2 = (const float*)d_in[base + 6];
    const float* wm_vb2 = (const float*)d_in[base + 7];
    const float* wm_cw  = (const float*)d_in[base + 8];
    const float* ws_sw1 = (const float*)d_in[base + 9];
    const float* ws_sb1 = (const float*)d_in[base + 10];
    const float* ws_sw2 = (const float*)d_in[base + 11];
    const float* ws_sb2 = (const float*)d_in[base + 12];
    const float* ws_vw1 = (const float*)d_in[base + 13];
    const float* ws_vb1 = (const float*)d_in[base + 14];
    const float* ws_vw2 = (const float*)d_in[base + 15];
    const float* ws_vb2 = (const float*)d_in[base + 16];
    const float* ws_cw  = (const float*)d_in[base + 17];
    const float* mx_cw  = (const float*)d_in[base + 18];
    const float* fin_w  = (const float*)d_in[base + 19];

    float *H, *Vwm, *Vws, *Swm, *Sws, *Awm, *Aws, *Amax, *R;
    cudaGetSymbolAddress((void**)&H,    g_H);
    cudaGetSymbolAddress((void**)&Vwm,  g_Vwm);
    cudaGetSymbolAddress((void**)&Vws,  g_Vws);
    cudaGetSymbolAddress((void**)&Swm,  g_Swm);
    cudaGetSymbolAddress((void**)&Sws,  g_Sws);
    cudaGetSymbolAddress((void**)&Awm,  g_Awm);
    cudaGetSymbolAddress((void**)&Aws,  g_Aws);
    cudaGetSymbolAddress((void**)&Amax, g_Amax);
    cudaGetSymbolAddress((void**)&R,    g_R);

    dim3 gridBig((N_NODES + 127) / 128, HID / 64);     // (1563, 4)
    dim3 gridG((N_GRAPHS + 127) / 128, OUT_DIM / 64);  // (16, 8)

    // ---- weighted_mean pooler node phase
    gemm128x64<true,  false, true ><<<gridBig, 256>>>(x, NODE_DIM, wm_sw1, HID, wm_sb1, H, HID, N_NODES, NODE_DIM);
    score_kernel<<<N_NODES / 8, 256>>>(H, wm_sw2, wm_sb2, Swm);
    gemm128x64<true,  false, true ><<<gridBig, 256>>>(x, NODE_DIM, wm_vw1, HID, wm_vb1, H, HID, N_NODES, NODE_DIM);
    gemm128x64<false, false, true ><<<gridBig, 256>>>(H, HID, wm_vw2, HID, wm_vb2, Vwm, HID, N_NODES, HID);

    // ---- weighted_sum pooler node phase
    gemm128x64<true,  false, true ><<<gridBig, 256>>>(x, NODE_DIM, ws_sw1, HID, ws_sb1, H, HID, N_NODES, NODE_DIM);
    score_kernel<<<N_NODES / 8, 256>>>(H, ws_sw2, ws_sb2, Sws);
    gemm128x64<true,  false, true ><<<gridBig, 256>>>(x, NODE_DIM, ws_vw1, HID, ws_vb1, H, HID, N_NODES, NODE_DIM);
    gemm128x64<false, false, true ><<<gridBig, 256>>>(H, HID, ws_vw2, HID, ws_vb2, Vws, HID, N_NODES, HID);

    // ---- segment reductions
    detect_seg<<<1, 32>>>((const int*)seg);
    graph_bounds<<<(N_GRAPHS + 256) / 256, 256>>>(seg);
    accumulate_kernel<<<N_GRAPHS, 256>>>(x);

    // ---- per-graph combines into R = [mean | sum | max] (pre-relu)
    gemm128x64<false, false, false><<<gridG, 256>>>(Awm,  HID, wm_cw, OUT_DIM, nullptr, R,        3 * OUT_DIM, N_GRAPHS, HID);
    gemm128x64<false, false, false><<<gridG, 256>>>(Aws,  HID, ws_cw, OUT_DIM, nullptr, R + 512,  3 * OUT_DIM, N_GRAPHS, HID);
    gemm128x64<false, false, false><<<gridG, 256>>>(Amax, HID, mx_cw, OUT_DIM, nullptr, R + 1024, 3 * OUT_DIM, N_GRAPHS, HID);

    // ---- final: out = relu(R) @ final_w
    gemm128x64<false, true,  false><<<gridG, 256>>>(R, 3 * OUT_DIM, fin_w, OUT_DIM, nullptr,
                                                    (float*)d_out, OUT_DIM, N_GRAPHS, 3 * OUT_DIM);
}

// round 5
// speedup vs baseline: 2.4750x; 2.4750x over previous
#include <cuda_runtime.h>
#include <math.h>
#include <stdint.h>

#define N_NODES   200000
#define NODE_DIM  256
#define OUT_DIM   512
#define NUM_HEADS 8
#define HEAD_DIM  32
#define HID       256
#define N_GRAPHS  2000

// ---------------- scratch (static device globals; no runtime allocation) ----
__device__ float g_H   [(size_t)N_NODES * HID];       // hidden scratch (reused)
__device__ float g_Vwm [(size_t)N_NODES * HID];       // wm values
__device__ float g_Vws [(size_t)N_NODES * HID];       // ws values
__device__ float g_Swm [(size_t)N_NODES * NUM_HEADS]; // wm scores
__device__ float g_Sws [(size_t)N_NODES * NUM_HEADS]; // ws scores
__device__ int   g_gstart[N_GRAPHS + 1];
__device__ int   g_seg64;
__device__ float g_Awm [(size_t)N_GRAPHS * HID];
__device__ float g_Aws [(size_t)N_GRAPHS * HID];
__device__ float g_Amax[(size_t)N_GRAPHS * HID];
__device__ float g_R   [(size_t)N_GRAPHS * 3 * OUT_DIM];

// ---------------- tf32 helpers ----------------------------------------------
__device__ __forceinline__ uint32_t f2tf32(float f) {
    uint32_t u;
    asm("cvt.rna.tf32.f32 %0, %1;" : "=r"(u) : "f"(f));
    return u;
}

__device__ __forceinline__ void mma_tf32(float* c, const uint32_t* a, const uint32_t* b) {
    asm volatile(
        "mma.sync.aligned.m16n8k8.row.col.f32.tf32.tf32.f32 "
        "{%0,%1,%2,%3}, {%4,%5,%6,%7}, {%8,%9}, {%0,%1,%2,%3};"
        : "+f"(c[0]), "+f"(c[1]), "+f"(c[2]), "+f"(c[3])
        : "r"(a[0]), "r"(a[1]), "r"(a[2]), "r"(a[3]), "r"(b[0]), "r"(b[1]));
}

// ---------------- tensor-core GEMM: C[M,N] = op(A[M,K]) @ W[K,N] (+bias) -----
// BM=128, BN=128, BK=32. 256 threads = 8 warps in 2(m) x 4(n); warp tile 64x32.
// blockIdx.x = n-block (so both n-blocks of one A tile are L2-adjacent),
// blockIdx.y = m-block. K must be a multiple of 32, N a multiple of 128.
template<bool RELU_OUT, bool RELU_IN, bool HAS_BIAS>
__global__ __launch_bounds__(256)
void tgemm(const float* __restrict__ A, int lda,
           const float* __restrict__ W, int ldw,
           const float* __restrict__ bias,
           float* __restrict__ C, int ldc,
           int M, int K)
{
    // stride 36: fragment-read banks (4g+t) unique -> conflict-free
    __shared__ uint32_t As[128][36];
    // stride 136: fragment-read banks (8t+8ni+g) unique -> conflict-free
    __shared__ uint32_t Bs[32][136];

    const int tid   = threadIdx.x;
    const int lane  = tid & 31;
    const int wid   = tid >> 5;
    const int warpM = wid & 1;        // 0..1  -> 64 rows each
    const int warpN = wid >> 1;       // 0..3  -> 32 cols each
    const int g     = lane >> 2;      // 0..7
    const int t     = lane & 3;       // 0..3
    const int bm    = blockIdx.y * 128;
    const int bn    = blockIdx.x * 128;

    float acc[4][4][4];
    #pragma unroll
    for (int mi = 0; mi < 4; mi++)
        #pragma unroll
        for (int ni = 0; ni < 4; ni++)
            #pragma unroll
            for (int q = 0; q < 4; q++) acc[mi][ni][q] = 0.0f;

    // prefetch registers
    float4 pa[4], pb[4];

    const int arow = tid >> 3;          // 0..31
    const int acol = (tid & 7) * 4;     // 0,4,...,28
    const int bcol = (lane) * 4;        // 0..124 within the 128-wide tile

    // ---- load tile (k0) into registers
    auto LOAD = [&](int k0) {
        #pragma unroll
        for (int j = 0; j < 4; j++) {
            int row = j * 32 + arow;
            int grow = bm + row; if (grow >= M) grow = M - 1;
            pa[j] = *reinterpret_cast<const float4*>(A + (size_t)grow * lda + k0 + acol);
        }
        #pragma unroll
        for (int j = 0; j < 4; j++) {
            int krow = j * 8 + wid;
            pb[j] = *reinterpret_cast<const float4*>(W + (size_t)(k0 + krow) * ldw + bn + bcol);
        }
    };

    // ---- convert + store registers into smem
    auto STORE = [&]() {
        #pragma unroll
        for (int j = 0; j < 4; j++) {
            int row = j * 32 + arow;
            float4 v = pa[j];
            if (RELU_IN) {
                v.x = fmaxf(v.x, 0.f); v.y = fmaxf(v.y, 0.f);
                v.z = fmaxf(v.z, 0.f); v.w = fmaxf(v.w, 0.f);
            }
            As[row][acol + 0] = f2tf32(v.x);
            As[row][acol + 1] = f2tf32(v.y);
            As[row][acol + 2] = f2tf32(v.z);
            As[row][acol + 3] = f2tf32(v.w);
        }
        #pragma unroll
        for (int j = 0; j < 4; j++) {
            int krow = j * 8 + wid;
            Bs[krow][bcol + 0] = f2tf32(pb[j].x);
            Bs[krow][bcol + 1] = f2tf32(pb[j].y);
            Bs[krow][bcol + 2] = f2tf32(pb[j].z);
            Bs[krow][bcol + 3] = f2tf32(pb[j].w);
        }
    };

    LOAD(0);
    for (int k0 = 0; k0 < K; k0 += 32) {
        STORE();
        __syncthreads();
        if (k0 + 32 < K) LOAD(k0 + 32);   // overlap global latency with MMAs

        #pragma unroll
        for (int kk = 0; kk < 4; kk++) {
            uint32_t af[4][4], bf[4][2];
            #pragma unroll
            for (int mi = 0; mi < 4; mi++) {
                int r0 = warpM * 64 + mi * 16;
                af[mi][0] = As[r0 + g    ][kk * 8 + t    ];
                af[mi][1] = As[r0 + 8 + g][kk * 8 + t    ];
                af[mi][2] = As[r0 + g    ][kk * 8 + t + 4];
                af[mi][3] = As[r0 + 8 + g][kk * 8 + t + 4];
            }
            #pragma unroll
            for (int ni = 0; ni < 4; ni++) {
                int c0 = warpN * 32 + ni * 8 + g;
                bf[ni][0] = Bs[kk * 8 + t    ][c0];
                bf[ni][1] = Bs[kk * 8 + t + 4][c0];
            }
            #pragma unroll
            for (int mi = 0; mi < 4; mi++)
                #pragma unroll
                for (int ni = 0; ni < 4; ni++)
                    mma_tf32(acc[mi][ni], af[mi], bf[ni]);
        }
        __syncthreads();
    }

    // ---- epilogue
    #pragma unroll
    for (int mi = 0; mi < 4; mi++) {
        int row0 = bm + warpM * 64 + mi * 16 + g;
        #pragma unroll
        for (int ni = 0; ni < 4; ni++) {
            int col = bn + warpN * 32 + ni * 8 + 2 * t;
            float b0 = 0.f, b1 = 0.f;
            if (HAS_BIAS) { b0 = bias[col]; b1 = bias[col + 1]; }
            float2 v0, v1;
            v0.x = acc[mi][ni][0] + b0; v0.y = acc[mi][ni][1] + b1;
            v1.x = acc[mi][ni][2] + b0; v1.y = acc[mi][ni][3] + b1;
            if (RELU_OUT) {
                v0.x = fmaxf(v0.x, 0.f); v0.y = fmaxf(v0.y, 0.f);
                v1.x = fmaxf(v1.x, 0.f); v1.y = fmaxf(v1.y, 0.f);
            }
            if (row0 < M)
                *reinterpret_cast<float2*>(C + (size_t)row0 * ldc + col) = v0;
            if (row0 + 8 < M)
                *reinterpret_cast<float2*>(C + (size_t)(row0 + 8) * ldc + col) = v1;
        }
    }
}

// ---------------- score layer: S[N,8] = H[N,256] @ w2[256,8] + b2 ------------
__global__ __launch_bounds__(256)
void score_kernel(const float* __restrict__ H, const float* __restrict__ w2,
                  const float* __restrict__ b2, float* __restrict__ S)
{
    __shared__ float w2s[HID * NUM_HEADS];
    __shared__ float b2s[NUM_HEADS];
    int tid = threadIdx.x;
    for (int i = tid; i < HID * NUM_HEADS; i += 256) w2s[i] = w2[i];
    if (tid < NUM_HEADS) b2s[tid] = b2[tid];
    __syncthreads();

    int warp = tid >> 5, lane = tid & 31;
    int node = blockIdx.x * 8 + warp;
    if (node >= N_NODES) return;

    float acc[NUM_HEADS];
    #pragma unroll
    for (int j = 0; j < NUM_HEADS; j++) acc[j] = 0.f;

    const float* h = H + (size_t)node * HID;
    #pragma unroll
    for (int r = 0; r < 8; r++) {
        int k = r * 32 + lane;
        float hv = h[k];
        #pragma unroll
        for (int j = 0; j < NUM_HEADS; j++) acc[j] = fmaf(hv, w2s[k * NUM_HEADS + j], acc[j]);
    }
    #pragma unroll
    for (int j = 0; j < NUM_HEADS; j++) {
        float v = acc[j];
        #pragma unroll
        for (int off = 16; off; off >>= 1) v += __shfl_xor_sync(0xFFFFFFFFu, v, off);
        if (lane == j) S[(size_t)node * NUM_HEADS + j] = v + b2s[j];
    }
}

// ---------------- seg dtype detection (int64 vs int32) -----------------------
__global__ void detect_seg(const int* __restrict__ p32)
{
    if (blockIdx.x == 0 && threadIdx.x == 0) {
        int nz = 0;
        for (int i = 4000; i < 5000; i++) nz |= p32[2 * i + 1];
        g_seg64 = (nz == 0) ? 1 : 0;
    }
}

// ---------------- graph ranges (seg is sorted) -------------------------------
__global__ void graph_bounds(const void* __restrict__ segv)
{
    int g = blockIdx.x * blockDim.x + threadIdx.x;
    if (g > N_GRAPHS) return;
    if (g == N_GRAPHS) { g_gstart[g] = N_NODES; return; }
    const int is64 = g_seg64;
    const long long* p64 = (const long long*)segv;
    const int*       p32 = (const int*)segv;
    int lo = 0, hi = N_NODES;
    while (lo < hi) {
        int mid = (lo + hi) >> 1;
        long long v = is64 ? p64[mid] : (long long)p32[mid];
        if (v < (long long)g) lo = mid + 1; else hi = mid;
    }
    g_gstart[g] = lo;
}

// ---------------- per-graph accumulation (block per graph, 256 threads) ------
__global__ __launch_bounds__(256)
void accumulate_kernel(const float* __restrict__ X)
{
    int g   = blockIdx.x;
    int s0  = g_gstart[g], s1 = g_gstart[g + 1];
    int tid = threadIdx.x;
    int n   = s1 - s0;

    __shared__ float red[32][NUM_HEADS];
    __shared__ float mh[NUM_HEADS], inv[NUM_HEADS];

    if (n == 0) {
        g_Awm [(size_t)g * HID + tid] = 0.f;
        g_Aws [(size_t)g * HID + tid] = 0.f;
        g_Amax[(size_t)g * HID + tid] = 0.f;
        return;
    }

    int h0 = tid & 7, grp = tid >> 3;  // 32 groups x 8 heads
    float m = -INFINITY;
    for (int i = grp; i < n; i += 32)
        m = fmaxf(m, g_Swm[(size_t)(s0 + i) * NUM_HEADS + h0]);
    red[grp][h0] = m;
    __syncthreads();
    if (tid < NUM_HEADS) {
        float mm = -INFINITY;
        #pragma unroll
        for (int r = 0; r < 32; r++) mm = fmaxf(mm, red[r][tid]);
        mh[tid] = mm;
    }
    __syncthreads();
    float mloc = mh[h0];
    float se = 0.f;
    for (int i = grp; i < n; i += 32)
        se += __expf(g_Swm[(size_t)(s0 + i) * NUM_HEADS + h0] - mloc);
    red[grp][h0] = se;
    __syncthreads();
    if (tid < NUM_HEADS) {
        float s = 0.f;
        #pragma unroll
        for (int r = 0; r < 32; r++) s += red[r][tid];
        inv[tid] = 1.0f / s;
    }
    __syncthreads();

    int c = tid;
    int h = c >> 5;
    float mH = mh[h], invH = inv[h];
    float aw = 0.f, asum = 0.f, mx = -INFINITY;
    for (int i = s0; i < s1; i++) {
        float sw = g_Swm[(size_t)i * NUM_HEADS + h];
        float ww = __expf(sw - mH) * invH;
        float ss = g_Sws[(size_t)i * NUM_HEADS + h];
        float ws = 1.0f / (1.0f + __expf(-ss));
        aw   = fmaf(ww, g_Vwm[(size_t)i * HID + c], aw);
        asum = fmaf(ws, g_Vws[(size_t)i * HID + c], asum);
        mx   = fmaxf(mx, X[(size_t)i * HID + c]);
    }
    g_Awm [(size_t)g * HID + c] = aw;
    g_Aws [(size_t)g * HID + c] = asum;
    g_Amax[(size_t)g * HID + c] = mx;
}

// ---------------- launch -----------------------------------------------------
extern "C" void kernel_launch(void* const* d_in, const int* in_sizes, int n_in,
                              void* d_out, int out_size)
{
    const float* x   = (const float*)d_in[0];
    const void*  seg = d_in[1];

    int base = 2;
    if (n_in >= 23 || (n_in > 2 && in_sizes[2] == 1)) base = 3;

    const float* wm_sw1 = (const float*)d_in[base + 0];
    const float* wm_sb1 = (const float*)d_in[base + 1];
    const float* wm_sw2 = (const float*)d_in[base + 2];
    const float* wm_sb2 = (const float*)d_in[base + 3];
    const float* wm_vw1 = (const float*)d_in[base + 4];
    const float* wm_vb1 = (const float*)d_in[base + 5];
    const float* wm_vw2 = (const float*)d_in[base + 6];
    const float* wm_vb2 = (const float*)d_in[base + 7];
    const float* wm_cw  = (const float*)d_in[base + 8];
    const float* ws_sw1 = (const float*)d_in[base + 9];
    const float* ws_sb1 = (const float*)d_in[base + 10];
    const float* ws_sw2 = (const float*)d_in[base + 11];
    const float* ws_sb2 = (const float*)d_in[base + 12];
    const float* ws_vw1 = (const float*)d_in[base + 13];
    const float* ws_vb1 = (const float*)d_in[base + 14];
    const float* ws_vw2 = (const float*)d_in[base + 15];
    const float* ws_vb2 = (const float*)d_in[base + 16];
    const float* ws_cw  = (const float*)d_in[base + 17];
    const float* mx_cw  = (const float*)d_in[base + 18];
    const float* fin_w  = (const float*)d_in[base + 19];

    float *H, *Vwm, *Vws, *Swm, *Sws, *Awm, *Aws, *Amax, *R;
    cudaGetSymbolAddress((void**)&H,    g_H);
    cudaGetSymbolAddress((void**)&Vwm,  g_Vwm);
    cudaGetSymbolAddress((void**)&Vws,  g_Vws);
    cudaGetSymbolAddress((void**)&Swm,  g_Swm);
    cudaGetSymbolAddress((void**)&Sws,  g_Sws);
    cudaGetSymbolAddress((void**)&Awm,  g_Awm);
    cudaGetSymbolAddress((void**)&Aws,  g_Aws);
    cudaGetSymbolAddress((void**)&Amax, g_Amax);
    cudaGetSymbolAddress((void**)&R,    g_R);

    const int MB_BIG = (N_NODES + 127) / 128;   // 1563
    const int MB_G   = (N_GRAPHS + 127) / 128;  // 16

    dim3 gridBig(HID / 128, MB_BIG);            // (2, 1563): x = n-block for L2 reuse
    dim3 gridG(OUT_DIM / 128, MB_G);            // (4, 16)

    // ---- weighted_mean pooler node phase
    tgemm<true,  false, true ><<<gridBig, 256>>>(x, NODE_DIM, wm_sw1, HID, wm_sb1, H, HID, N_NODES, NODE_DIM);
    score_kernel<<<N_NODES / 8, 256>>>(H, wm_sw2, wm_sb2, Swm);
    tgemm<true,  false, true ><<<gridBig, 256>>>(x, NODE_DIM, wm_vw1, HID, wm_vb1, H, HID, N_NODES, NODE_DIM);
    tgemm<false, false, true ><<<gridBig, 256>>>(H, HID, wm_vw2, HID, wm_vb2, Vwm, HID, N_NODES, HID);

    // ---- weighted_sum pooler node phase
    tgemm<true,  false, true ><<<gridBig, 256>>>(x, NODE_DIM, ws_sw1, HID, ws_sb1, H, HID, N_NODES, NODE_DIM);
    score_kernel<<<N_NODES / 8, 256>>>(H, ws_sw2, ws_sb2, Sws);
    tgemm<true,  false, true ><<<gridBig, 256>>>(x, NODE_DIM, ws_vw1, HID, ws_vb1, H, HID, N_NODES, NODE_DIM);
    tgemm<false, false, true ><<<gridBig, 256>>>(H, HID, ws_vw2, HID, ws_vb2, Vws, HID, N_NODES, HID);

    // ---- segment reductions
    detect_seg<<<1, 32>>>((const int*)seg);
    graph_bounds<<<(N_GRAPHS + 256) / 256, 256>>>(seg);
    accumulate_kernel<<<N_GRAPHS, 256>>>(x);

    // ---- per-graph combines into R = [mean | sum | max] (pre-relu)
    tgemm<false, false, false><<<gridG, 256>>>(Awm,  HID, wm_cw, OUT_DIM, nullptr, R,        3 * OUT_DIM, N_GRAPHS, HID);
    tgemm<false, false, false><<<gridG, 256>>>(Aws,  HID, ws_cw, OUT_DIM, nullptr, R + 512,  3 * OUT_DIM, N_GRAPHS, HID);
    tgemm<false, false, false><<<gridG, 256>>>(Amax, HID, mx_cw, OUT_DIM, nullptr, R + 1024, 3 * OUT_DIM, N_GRAPHS, HID);

    // ---- final: out = relu(R) @ final_w
    tgemm<false, true,  false><<<gridG, 256>>>(R, 3 * OUT_DIM, fin_w, OUT_DIM, nullptr,
                                               (float*)d_out, OUT_DIM, N_GRAPHS, 3 * OUT_DIM);
}